// round 5
// baseline (speedup 1.0000x reference)
#include <cuda_runtime.h>
#include <cuda_bf16.h>
#include <cstdint>

#define N_NODES 50000
#define N_EDGES 800000
#define FEAT    64
#define CAP     128

__device__ int g_cnt[N_NODES];
__device__ int g_slot[(size_t)N_NODES * CAP];

// ---------------------------------------------------------------------------
// Pass 1: bucket build. One thread per 4 edges (int4 loads).
// ---------------------------------------------------------------------------
__global__ void build_buckets_kernel(const int4* __restrict__ es4,
                                     const int4* __restrict__ ed4,
                                     int*        __restrict__ cnt,
                                     int*        __restrict__ slot)
{
    int t = blockIdx.x * blockDim.x + threadIdx.x;
    if (t >= N_EDGES / 4) return;
    int4 s = __ldg(es4 + t);
    int4 d = __ldg(ed4 + t);
    int p;
    p = atomicAdd(cnt + d.x, 1); if (p < CAP) slot[(size_t)d.x * CAP + p] = s.x;
    p = atomicAdd(cnt + d.y, 1); if (p < CAP) slot[(size_t)d.y * CAP + p] = s.y;
    p = atomicAdd(cnt + d.z, 1); if (p < CAP) slot[(size_t)d.z * CAP + p] = s.z;
    p = atomicAdd(cnt + d.w, 1); if (p < CAP) slot[(size_t)d.w * CAP + p] = s.w;
}

// ---------------------------------------------------------------------------
// Pass 2: one warp per TWO nodes (A and B), lane owns float2 chunk of each.
// All head loads (slotA, slotB, cntA, cntB, dstA, dstB) issue independently;
// gather loops for A and B are interleaved with predicated loads -> up to 16
// independent row reads in flight per warp per unrolled step.
// ---------------------------------------------------------------------------
#define WARPS_PER_BLOCK 8   // 256 threads -> 16 nodes/block; 50000/16 = 3125 exact

__global__ void __launch_bounds__(256)
gather_matmul_kernel(const float2* __restrict__ src2,
                     const float2* __restrict__ dst2,
                     const int*    __restrict__ cnt,
                     const int*    __restrict__ slot,
                     float*        __restrict__ out)
{
    __shared__ float S_sm[WARPS_PER_BLOCK][2][64];
    __shared__ float D_sm[WARPS_PER_BLOCK][2][64];

    int w    = threadIdx.x >> 5;
    int lane = threadIdx.x & 31;
    int nA   = (blockIdx.x * WARPS_PER_BLOCK + w) * 2;
    int nB   = nA + 1;

    const int* sbA = slot + (size_t)nA * CAP;
    const int* sbB = slot + (size_t)nB * CAP;

    // All six head loads are independent — no serial cnt->slot chain.
    // slot[lane] is always in-bounds (CAP=128); entries beyond cnt are stale
    // but never consumed (shfl only pulls lanes < kb).
    int    idxA = __ldg(sbA + lane);
    int    idxB = __ldg(sbB + lane);
    int    kA   = __ldg(cnt + nA);
    int    kB   = __ldg(cnt + nB);
    float2 dA   = __ldg(dst2 + (size_t)nA * 32 + lane);
    float2 dB   = __ldg(dst2 + (size_t)nB * 32 + lane);

    if (kA > CAP) kA = CAP;
    if (kB > CAP) kB = CAP;

    float2 accA = make_float2(0.f, 0.f);
    float2 accB = make_float2(0.f, 0.f);

#define GP(t) do {                                                        \
        int sA_ = __shfl_sync(0xffffffffu, idxA, j + (t));                \
        int sB_ = __shfl_sync(0xffffffffu, idxB, j + (t));                \
        if (j + (t) < kbA) {                                              \
            float2 v_ = __ldg(src2 + (size_t)sA_ * 32 + lane);            \
            accA.x += v_.x; accA.y += v_.y;                               \
        }                                                                 \
        if (j + (t) < kbB) {                                              \
            float2 v_ = __ldg(src2 + (size_t)sB_ * 32 + lane);            \
            accB.x += v_.x; accB.y += v_.y;                               \
        }                                                                 \
    } while (0)

    {
        int kbA = kA < 32 ? kA : 32;
        int kbB = kB < 32 ? kB : 32;
        int kmax = kbA > kbB ? kbA : kbB;
        int j = 0;
        for (; j + 8 <= kmax; j += 8) {
            GP(0); GP(1); GP(2); GP(3); GP(4); GP(5); GP(6); GP(7);
        }
        for (; j < kmax; ++j) {
            GP(0);
        }
    }

    // Rare fallback: degree > 32 (P ~ 1e-4 for Poisson(16)).
    if (kA > 32 || kB > 32) {
        int kmaxT = kA > kB ? kA : kB;
        for (int b = 32; b < kmaxT; b += 32) {
            idxA = __ldg(sbA + b + lane);       // b+lane <= 96+31 < CAP
            idxB = __ldg(sbB + b + lane);
            int kbA = kA - b; kbA = kbA < 0 ? 0 : (kbA > 32 ? 32 : kbA);
            int kbB = kB - b; kbB = kbB < 0 ? 0 : (kbB > 32 ? 32 : kbB);
            int kmax = kbA > kbB ? kbA : kbB;
            for (int j = 0; j < kmax; ++j) {
                GP(0);
            }
        }
    }
#undef GP

    // Stash S rows and dst rows, warp-local.
    S_sm[w][0][2 * lane]     = accA.x;
    S_sm[w][0][2 * lane + 1] = accA.y;
    S_sm[w][1][2 * lane]     = accB.x;
    S_sm[w][1][2 * lane + 1] = accB.y;
    D_sm[w][0][2 * lane]     = dA.x;
    D_sm[w][0][2 * lane + 1] = dA.y;
    D_sm[w][1][2 * lane]     = dB.x;
    D_sm[w][1][2 * lane + 1] = dB.y;
    __syncwarp();

    // out[i][j] = sum_p S[i][p] * D[p][j] / sqrt(8), for both nodes.
    int i  = lane >> 2;
    int jp = (lane & 3) * 2;
    float oA0 = 0.f, oA1 = 0.f, oB0 = 0.f, oB1 = 0.f;
    #pragma unroll
    for (int p = 0; p < 8; ++p) {
        float aA = S_sm[w][0][i * 8 + p];
        float aB = S_sm[w][1][i * 8 + p];
        oA0 = fmaf(aA, D_sm[w][0][p * 8 + jp],     oA0);
        oA1 = fmaf(aA, D_sm[w][0][p * 8 + jp + 1], oA1);
        oB0 = fmaf(aB, D_sm[w][1][p * 8 + jp],     oB0);
        oB1 = fmaf(aB, D_sm[w][1][p * 8 + jp + 1], oB1);
    }
    const float inv = 0.3535533905932737622f;  // 1/sqrt(8)
    reinterpret_cast<float2*>(out + (size_t)nA * FEAT)[lane] = make_float2(oA0 * inv, oA1 * inv);
    reinterpret_cast<float2*>(out + (size_t)nB * FEAT)[lane] = make_float2(oB0 * inv, oB1 * inv);
}

extern "C" void kernel_launch(void* const* d_in, const int* in_sizes, int n_in,
                              void* d_out, int out_size)
{
    const float* src_feat = (const float*)d_in[0];
    const float* dst_feat = (const float*)d_in[1];
    const int*   edge_src = (const int*)d_in[2];
    const int*   edge_dst = (const int*)d_in[3];
    float*       out      = (float*)d_out;

    void* cnt_ptr  = nullptr;
    void* slot_ptr = nullptr;
    cudaGetSymbolAddress(&cnt_ptr, g_cnt);
    cudaGetSymbolAddress(&slot_ptr, g_slot);

    cudaMemsetAsync(cnt_ptr, 0, (size_t)N_NODES * sizeof(int), 0);

    {
        int threads = 256;
        int work    = N_EDGES / 4;                 // 200000
        int blocks  = (work + threads - 1) / threads;
        build_buckets_kernel<<<blocks, threads>>>(
            reinterpret_cast<const int4*>(edge_src),
            reinterpret_cast<const int4*>(edge_dst),
            (int*)cnt_ptr, (int*)slot_ptr);
    }
    {
        int threads = WARPS_PER_BLOCK * 32;        // 256
        int blocks  = N_NODES / (WARPS_PER_BLOCK * 2);   // 3125 exact
        gather_matmul_kernel<<<blocks, threads>>>(
            reinterpret_cast<const float2*>(src_feat),
            reinterpret_cast<const float2*>(dst_feat),
            (const int*)cnt_ptr, (const int*)slot_ptr, out);
    }
}

// round 6
// speedup vs baseline: 1.0124x; 1.0124x over previous
#include <cuda_runtime.h>
#include <cuda_bf16.h>
#include <cstdint>

#define N_NODES 50000
#define N_EDGES 800000
#define FEAT    64
#define CAP     128

__device__ int g_cnt[N_NODES];   // zero-initialized at module load; gather resets it
__device__ int g_slot[(size_t)N_NODES * CAP];

// ---------------------------------------------------------------------------
// Pass 1: bucket build. One thread per 4 edges (int4 loads).
// ---------------------------------------------------------------------------
__global__ void build_buckets_kernel(const int4* __restrict__ es4,
                                     const int4* __restrict__ ed4,
                                     int*        __restrict__ cnt,
                                     int*        __restrict__ slot)
{
    int t = blockIdx.x * blockDim.x + threadIdx.x;
    if (t >= N_EDGES / 4) return;
    int4 s = __ldg(es4 + t);
    int4 d = __ldg(ed4 + t);
    int p;
    p = atomicAdd(cnt + d.x, 1); if (p < CAP) slot[(size_t)d.x * CAP + p] = s.x;
    p = atomicAdd(cnt + d.y, 1); if (p < CAP) slot[(size_t)d.y * CAP + p] = s.y;
    p = atomicAdd(cnt + d.z, 1); if (p < CAP) slot[(size_t)d.z * CAP + p] = s.z;
    p = atomicAdd(cnt + d.w, 1); if (p < CAP) slot[(size_t)d.w * CAP + p] = s.w;
}

// ---------------------------------------------------------------------------
// Pass 2: 16 threads per node, thread owns one float4 chunk (LDG.128: each
// warp fetches 2 rows / 512B per instruction). Slot indices arrive as 2x int4
// broadcast loads, software-pipelined one batch ahead. Gathers predicated.
// After reading cnt[n], resets it to 0 for the next graph replay.
// ---------------------------------------------------------------------------
#define NODES_PER_BLOCK 16   // 256 threads; 50000/16 = 3125 exact blocks

__global__ void __launch_bounds__(256)
gather_matmul_kernel(const float4* __restrict__ src4,
                     const float4* __restrict__ dst4,
                     int*          __restrict__ cnt,
                     const int*    __restrict__ slot,
                     float*        __restrict__ out)
{
    __shared__ float  S_sm[NODES_PER_BLOCK][68];   // padded rows
    __shared__ float4 D_sm[NODES_PER_BLOCK][18];

    int local = threadIdx.x >> 4;          // node within block
    int c     = threadIdx.x & 15;          // float4 chunk of the 64-float row
    int n     = blockIdx.x * NODES_PER_BLOCK + local;   // exact grid: n < N_NODES

    const int4* sb4 = reinterpret_cast<const int4*>(slot + (size_t)n * CAP);

    // Independent head loads: cnt, first 8 slot indices, dst row. Slot reads
    // beyond cnt are stale-but-valid node ids (never accumulated).
    int    k  = __ldg(cnt + n);
    int4   i0 = __ldg(sb4);
    int4   i1 = __ldg(sb4 + 1);
    float4 dr = __ldg(dst4 + (size_t)n * 16 + c);

    if (c == 0) cnt[n] = 0;                // reset for next replay
    if (k > CAP) k = CAP;

    float4 acc = make_float4(0.f, 0.f, 0.f, 0.f);

#define GACC(IDX, T) do {                                                  \
        if (r > (T)) {                                                     \
            float4 v_ = __ldg(src4 + (size_t)(IDX) * 16 + c);              \
            acc.x += v_.x; acc.y += v_.y; acc.z += v_.z; acc.w += v_.w;    \
        }                                                                  \
    } while (0)

    for (int b = 0; b < k; b += 8) {
        // Prefetch next batch's indices while this batch's gathers fly.
        int4 n0, n1;
        bool more = (b + 8 < k) && (b + 16 <= CAP);
        if (more) {
            n0 = __ldg(sb4 + (b >> 2) + 2);
            n1 = __ldg(sb4 + (b >> 2) + 3);
        }
        int r = k - b;
        GACC(i0.x, 0); GACC(i0.y, 1); GACC(i0.z, 2); GACC(i0.w, 3);
        GACC(i1.x, 4); GACC(i1.y, 5); GACC(i1.z, 6); GACC(i1.w, 7);
        if (more) { i0 = n0; i1 = n1; }
    }
#undef GACC

    *reinterpret_cast<float4*>(&S_sm[local][c * 4]) = acc;
    D_sm[local][c] = dr;
    __syncthreads();

    // out[i][j] = sum_p S[i][p] * D[p][j] / sqrt(8)
    {
        int i  = c >> 1;
        int jh = c & 1;
        float4 o = make_float4(0.f, 0.f, 0.f, 0.f);
        #pragma unroll
        for (int p = 0; p < 8; ++p) {
            float  a = S_sm[local][i * 8 + p];
            float4 b = D_sm[local][p * 2 + jh];
            o.x = fmaf(a, b.x, o.x);
            o.y = fmaf(a, b.y, o.y);
            o.z = fmaf(a, b.z, o.z);
            o.w = fmaf(a, b.w, o.w);
        }
        const float inv = 0.3535533905932737622f;   // 1/sqrt(8)
        o.x *= inv; o.y *= inv; o.z *= inv; o.w *= inv;
        reinterpret_cast<float4*>(out + (size_t)n * FEAT)[c] = o;
    }
}

extern "C" void kernel_launch(void* const* d_in, const int* in_sizes, int n_in,
                              void* d_out, int out_size)
{
    const float* src_feat = (const float*)d_in[0];
    const float* dst_feat = (const float*)d_in[1];
    const int*   edge_src = (const int*)d_in[2];
    const int*   edge_dst = (const int*)d_in[3];
    float*       out      = (float*)d_out;

    void* cnt_ptr  = nullptr;
    void* slot_ptr = nullptr;
    cudaGetSymbolAddress(&cnt_ptr, g_cnt);
    cudaGetSymbolAddress(&slot_ptr, g_slot);

    // No memset: g_cnt starts zeroed (module load) and gather_matmul_kernel
    // resets it every launch, keeping the invariant across graph replays.

    {
        int threads = 256;
        int work    = N_EDGES / 4;                 // 200000
        int blocks  = (work + threads - 1) / threads;
        build_buckets_kernel<<<blocks, threads>>>(
            reinterpret_cast<const int4*>(edge_src),
            reinterpret_cast<const int4*>(edge_dst),
            (int*)cnt_ptr, (int*)slot_ptr);
    }
    {
        int threads = NODES_PER_BLOCK * 16;        // 256
        int blocks  = N_NODES / NODES_PER_BLOCK;   // 3125 exact
        gather_matmul_kernel<<<blocks, threads>>>(
            reinterpret_cast<const float4*>(src_feat),
            reinterpret_cast<const float4*>(dst_feat),
            (int*)cnt_ptr, (const int*)slot_ptr, out);
    }
}

// round 7
// speedup vs baseline: 1.0936x; 1.0802x over previous
#include <cuda_runtime.h>
#include <cuda_bf16.h>
#include <cstdint>

#define N_NODES 50000
#define N_EDGES 800000
#define FEAT    64
#define CAP     128

__device__ int g_cnt[N_NODES];   // zeroed at module load; gather resets it each launch
__device__ int g_slot[(size_t)N_NODES * CAP];

// ---------------------------------------------------------------------------
// Pass 1: bucket build. One thread per 4 edges (int4 loads).
// ---------------------------------------------------------------------------
__global__ void build_buckets_kernel(const int4* __restrict__ es4,
                                     const int4* __restrict__ ed4,
                                     int*        __restrict__ cnt,
                                     int*        __restrict__ slot)
{
    int t = blockIdx.x * blockDim.x + threadIdx.x;
    if (t >= N_EDGES / 4) return;
    int4 s = __ldg(es4 + t);
    int4 d = __ldg(ed4 + t);
    int p;
    p = atomicAdd(cnt + d.x, 1); if (p < CAP) slot[(size_t)d.x * CAP + p] = s.x;
    p = atomicAdd(cnt + d.y, 1); if (p < CAP) slot[(size_t)d.y * CAP + p] = s.y;
    p = atomicAdd(cnt + d.z, 1); if (p < CAP) slot[(size_t)d.z * CAP + p] = s.z;
    p = atomicAdd(cnt + d.w, 1); if (p < CAP) slot[(size_t)d.w * CAP + p] = s.w;
}

// ---------------------------------------------------------------------------
// Pass 2 (fused): per node, gather+sum source rows from the contiguous slot
// list (R3 structure — compiler batches the 8 independent row loads), then
// 8x8 @ 8x8 matmul vs dst_feat[n]. 16 threads/node, one float4 chunk each.
// __launch_bounds__(256, 8) forces regs<=32 for high occupancy.
// ---------------------------------------------------------------------------
#define NODES_PER_BLOCK 16   // 256 threads; 50000/16 = 3125 exact blocks

__global__ void __launch_bounds__(256, 8)
gather_matmul_kernel(const float4* __restrict__ src4,
                     const float4* __restrict__ dst4,
                     int*          __restrict__ cnt,
                     const int*    __restrict__ slot,
                     float*        __restrict__ out)
{
    __shared__ float  S_sm[NODES_PER_BLOCK][68];   // padded rows
    __shared__ float4 D_sm[NODES_PER_BLOCK][18];

    int local = threadIdx.x >> 4;
    int c     = threadIdx.x & 15;
    int n     = blockIdx.x * NODES_PER_BLOCK + local;   // exact grid

    int k = __ldg(cnt + n);
    if (c == 0) cnt[n] = 0;                // reset for next graph replay
    if (k > CAP) k = CAP;
    const int4* sl4 = reinterpret_cast<const int4*>(slot + (size_t)n * CAP);

    float4 acc = make_float4(0.f, 0.f, 0.f, 0.f);

    int j = 0;
    // 8-wide unroll: 8 independent 256B row gathers in flight per group.
    for (; j + 8 <= k; j += 8) {
        int4 s0 = __ldg(sl4 + (j >> 2));
        int4 s1 = __ldg(sl4 + (j >> 2) + 1);
        float4 v0 = __ldg(src4 + (size_t)s0.x * 16 + c);
        float4 v1 = __ldg(src4 + (size_t)s0.y * 16 + c);
        float4 v2 = __ldg(src4 + (size_t)s0.z * 16 + c);
        float4 v3 = __ldg(src4 + (size_t)s0.w * 16 + c);
        float4 v4 = __ldg(src4 + (size_t)s1.x * 16 + c);
        float4 v5 = __ldg(src4 + (size_t)s1.y * 16 + c);
        float4 v6 = __ldg(src4 + (size_t)s1.z * 16 + c);
        float4 v7 = __ldg(src4 + (size_t)s1.w * 16 + c);
        acc.x += (v0.x + v1.x) + (v2.x + v3.x) + ((v4.x + v5.x) + (v6.x + v7.x));
        acc.y += (v0.y + v1.y) + (v2.y + v3.y) + ((v4.y + v5.y) + (v6.y + v7.y));
        acc.z += (v0.z + v1.z) + (v2.z + v3.z) + ((v4.z + v5.z) + (v6.z + v7.z));
        acc.w += (v0.w + v1.w) + (v2.w + v3.w) + ((v4.w + v5.w) + (v6.w + v7.w));
    }
    if (j + 4 <= k) {
        int4 s0 = __ldg(sl4 + (j >> 2));
        float4 v0 = __ldg(src4 + (size_t)s0.x * 16 + c);
        float4 v1 = __ldg(src4 + (size_t)s0.y * 16 + c);
        float4 v2 = __ldg(src4 + (size_t)s0.z * 16 + c);
        float4 v3 = __ldg(src4 + (size_t)s0.w * 16 + c);
        acc.x += (v0.x + v1.x) + (v2.x + v3.x);
        acc.y += (v0.y + v1.y) + (v2.y + v3.y);
        acc.z += (v0.z + v1.z) + (v2.z + v3.z);
        acc.w += (v0.w + v1.w) + (v2.w + v3.w);
        j += 4;
    }
    for (; j < k; ++j) {
        int s = __ldg(slot + (size_t)n * CAP + j);
        float4 v = __ldg(src4 + (size_t)s * 16 + c);
        acc.x += v.x; acc.y += v.y; acc.z += v.z; acc.w += v.w;
    }

    *reinterpret_cast<float4*>(&S_sm[local][c * 4]) = acc;
    D_sm[local][c] = __ldg(dst4 + (size_t)n * 16 + c);
    __syncthreads();

    {
        int i  = c >> 1;
        int jh = c & 1;
        float4 o = make_float4(0.f, 0.f, 0.f, 0.f);
        #pragma unroll
        for (int p = 0; p < 8; ++p) {
            float  a = S_sm[local][i * 8 + p];
            float4 b = D_sm[local][p * 2 + jh];
            o.x = fmaf(a, b.x, o.x);
            o.y = fmaf(a, b.y, o.y);
            o.z = fmaf(a, b.z, o.z);
            o.w = fmaf(a, b.w, o.w);
        }
        const float inv = 0.3535533905932737622f;   // 1/sqrt(8)
        o.x *= inv; o.y *= inv; o.z *= inv; o.w *= inv;
        reinterpret_cast<float4*>(out + (size_t)n * FEAT)[c] = o;
    }
}

extern "C" void kernel_launch(void* const* d_in, const int* in_sizes, int n_in,
                              void* d_out, int out_size)
{
    const float* src_feat = (const float*)d_in[0];
    const float* dst_feat = (const float*)d_in[1];
    const int*   edge_src = (const int*)d_in[2];
    const int*   edge_dst = (const int*)d_in[3];
    float*       out      = (float*)d_out;

    void* cnt_ptr  = nullptr;
    void* slot_ptr = nullptr;
    cudaGetSymbolAddress(&cnt_ptr, g_cnt);
    cudaGetSymbolAddress(&slot_ptr, g_slot);

    // No memset: g_cnt starts zeroed (module load) and gather_matmul_kernel
    // resets it every launch, keeping the invariant across graph replays.

    {
        int threads = 256;
        int work    = N_EDGES / 4;                 // 200000
        int blocks  = (work + threads - 1) / threads;
        build_buckets_kernel<<<blocks, threads>>>(
            reinterpret_cast<const int4*>(edge_src),
            reinterpret_cast<const int4*>(edge_dst),
            (int*)cnt_ptr, (int*)slot_ptr);
    }
    {
        int threads = NODES_PER_BLOCK * 16;        // 256
        int blocks  = N_NODES / NODES_PER_BLOCK;   // 3125 exact
        gather_matmul_kernel<<<blocks, threads>>>(
            reinterpret_cast<const float4*>(src_feat),
            reinterpret_cast<const float4*>(dst_feat),
            (int*)cnt_ptr, (const int*)slot_ptr, out);
    }
}